// round 1
// baseline (speedup 1.0000x reference)
#include <cuda_runtime.h>
#include <math.h>

#define NND 100000
#define NE  3200000
#define LTOK 64
#define HID 16
#define EF  5

// ---- scratch (device globals; no allocation allowed) ----
__device__ float g_dinv[NND];
__device__ int   g_deg[NND];
__device__ float g_M1[NND * HID];
__device__ float g_M2[NND * HID];
__device__ float g_agg1[NND * HID];
__device__ float g_agg2[NND * HID];
__device__ float g_A[NND * HID];
__device__ float g_B[NND * HID];

__device__ __forceinline__ void red_add_v4(float* p, float4 v) {
    asm volatile("red.global.add.v4.f32 [%0], {%1, %2, %3, %4};"
                 :: "l"(p), "f"(v.x), "f"(v.y), "f"(v.z), "f"(v.w) : "memory");
}

// ---------------- K0: zero scratch ----------------
__global__ void k_zero() {
    int i = blockIdx.x * blockDim.x + threadIdx.x;
    int stride = gridDim.x * blockDim.x;
    float4* a1 = reinterpret_cast<float4*>(g_agg1);
    float4* a2 = reinterpret_cast<float4*>(g_agg2);
    const int n4 = NND * HID / 4;
    float4 z = make_float4(0.f, 0.f, 0.f, 0.f);
    for (int j = i; j < n4; j += stride) { a1[j] = z; a2[j] = z; }
    for (int j = i; j < NND; j += stride) g_deg[j] = 0;
}

// ---------------- K1: degree ----------------
__global__ void k_degree(const int* __restrict__ ei, const int* __restrict__ batch) {
    int e = blockIdx.x * blockDim.x + threadIdx.x;
    if (e >= NE) return;
    int s = ei[e];
    int d = ei[NE + e];
    if (batch[s] == batch[d]) atomicAdd(&g_deg[s], 1);
}

// ---------------- K2: encode nodes + dinv + M1 = X@w1+b1 ----------------
__global__ void k_encode(const int* __restrict__ seq, const float* __restrict__ xcov,
                         const float* __restrict__ embed, const float* __restrict__ w1,
                         const float* __restrict__ b1) {
    __shared__ float s_emb[6 * 16];
    __shared__ float s_w1[17 * 16];
    __shared__ float s_b1[16];
    int t = threadIdx.x;
    for (int j = t; j < 96; j += blockDim.x) s_emb[j] = embed[j];
    for (int j = t; j < 272; j += blockDim.x) s_w1[j] = w1[j];
    if (t < 16) s_b1[t] = b1[t];
    __syncthreads();

    int n = blockIdx.x * blockDim.x + t;
    if (n >= NND) return;

    float dinv = rsqrtf((float)g_deg[n] + 1.0f + 1e-8f);
    g_dinv[n] = dinv;

    float acc[16];
#pragma unroll
    for (int k = 0; k < 16; k++) acc[k] = 0.f;
    int cnt = 0;

    const int4* tp = reinterpret_cast<const int4*>(seq + (long)n * LTOK);
#pragma unroll
    for (int i = 0; i < 16; i++) {
        int4 v = tp[i];
        int tok[4] = {v.x, v.y, v.z, v.w};
#pragma unroll
        for (int j = 0; j < 4; j++) {
            int tk = tok[j];
            cnt += (tk != 0);
            const float* er = &s_emb[tk * 16];  // row 0 is all-zero in data
#pragma unroll
            for (int k = 0; k < 16; k++) acc[k] += er[k];
        }
    }
    float inv = 1.0f / fmaxf((float)cnt, 1.0f);

    float x[17];
#pragma unroll
    for (int k = 0; k < 16; k++) x[k] = acc[k] * inv;
    x[16] = xcov[n];

    float m[16];
#pragma unroll
    for (int k = 0; k < 16; k++) {
        float s = s_b1[k];
#pragma unroll
        for (int j = 0; j < 17; j++) s += x[j] * s_w1[j * 16 + k];
        m[k] = s;
    }
    float4* mp = reinterpret_cast<float4*>(&g_M1[n * 16]);
    mp[0] = make_float4(m[0], m[1], m[2], m[3]);
    mp[1] = make_float4(m[4], m[5], m[6], m[7]);
    mp[2] = make_float4(m[8], m[9], m[10], m[11]);
    mp[3] = make_float4(m[12], m[13], m[14], m[15]);
}

// ---------------- K3/K5: edge aggregation (scatter-add) ----------------
template <int LAYER>
__global__ void k_aggregate(const int* __restrict__ ei, const int* __restrict__ batch) {
    int e = blockIdx.x * blockDim.x + threadIdx.x;
    if (e >= NE) return;
    int s = ei[e];
    int d = ei[NE + e];
    if (batch[s] != batch[d]) return;
    float c = g_dinv[d];
    const float* M = (LAYER == 0) ? g_M1 : g_M2;
    float* agg = (LAYER == 0) ? g_agg1 : g_agg2;
    const float4* mp = reinterpret_cast<const float4*>(M + d * 16);
    float* ap = agg + s * 16;
#pragma unroll
    for (int i = 0; i < 4; i++) {
        float4 v = mp[i];
        v.x *= c; v.y *= c; v.z *= c; v.w *= c;
        red_add_v4(ap + 4 * i, v);
    }
}

// ---------------- K4: finalize layer1 -> M2 = relu(...)@w2+b2 ----------------
__global__ void k_finalize1(const float* __restrict__ w2, const float* __restrict__ b2) {
    __shared__ float sW[16 * 16];
    __shared__ float sb[16];
    int t = threadIdx.x;
    for (int j = t; j < 256; j += blockDim.x) sW[j] = w2[j];
    if (t < 16) sb[t] = b2[t];
    __syncthreads();

    int n = blockIdx.x * blockDim.x + t;
    if (n >= NND) return;
    float dinv = g_dinv[n];
    const float4* ap = reinterpret_cast<const float4*>(g_agg1 + n * 16);
    const float4* mp = reinterpret_cast<const float4*>(g_M1 + n * 16);
    float h[16];
#pragma unroll
    for (int i = 0; i < 4; i++) {
        float4 a = ap[i], m = mp[i];
        h[4 * i + 0] = fmaxf(dinv * (a.x + dinv * m.x), 0.f);
        h[4 * i + 1] = fmaxf(dinv * (a.y + dinv * m.y), 0.f);
        h[4 * i + 2] = fmaxf(dinv * (a.z + dinv * m.z), 0.f);
        h[4 * i + 3] = fmaxf(dinv * (a.w + dinv * m.w), 0.f);
    }
    float m2[16];
#pragma unroll
    for (int k = 0; k < 16; k++) {
        float s = sb[k];
#pragma unroll
        for (int j = 0; j < 16; j++) s += h[j] * sW[j * 16 + k];
        m2[k] = s;
    }
    float4* op = reinterpret_cast<float4*>(&g_M2[n * 16]);
    op[0] = make_float4(m2[0], m2[1], m2[2], m2[3]);
    op[1] = make_float4(m2[4], m2[5], m2[6], m2[7]);
    op[2] = make_float4(m2[8], m2[9], m2[10], m2[11]);
    op[3] = make_float4(m2[12], m2[13], m2[14], m2[15]);
}

// ---------------- K6: finalize layer2 -> A = H@we1[0:16]+be1, B = H@we1[16:32] ----------------
__global__ void k_finalize2(const float* __restrict__ we1, const float* __restrict__ be1) {
    __shared__ float sW[32 * 16];
    __shared__ float sb[16];
    int t = threadIdx.x;
    for (int j = t; j < 512; j += blockDim.x) sW[j] = we1[j];
    if (t < 16) sb[t] = be1[t];
    __syncthreads();

    int n = blockIdx.x * blockDim.x + t;
    if (n >= NND) return;
    float dinv = g_dinv[n];
    const float4* ap = reinterpret_cast<const float4*>(g_agg2 + n * 16);
    const float4* mp = reinterpret_cast<const float4*>(g_M2 + n * 16);
    float h[16];
#pragma unroll
    for (int i = 0; i < 4; i++) {
        float4 a = ap[i], m = mp[i];
        h[4 * i + 0] = fmaxf(dinv * (a.x + dinv * m.x), 0.f);
        h[4 * i + 1] = fmaxf(dinv * (a.y + dinv * m.y), 0.f);
        h[4 * i + 2] = fmaxf(dinv * (a.z + dinv * m.z), 0.f);
        h[4 * i + 3] = fmaxf(dinv * (a.w + dinv * m.w), 0.f);
    }
    float av[16], bv[16];
#pragma unroll
    for (int k = 0; k < 16; k++) {
        float sa = sb[k];
        float sbv = 0.f;
#pragma unroll
        for (int j = 0; j < 16; j++) {
            sa  += h[j] * sW[j * 16 + k];
            sbv += h[j] * sW[(16 + j) * 16 + k];
        }
        av[k] = sa; bv[k] = sbv;
    }
    float4* oa = reinterpret_cast<float4*>(&g_A[n * 16]);
    float4* ob = reinterpret_cast<float4*>(&g_B[n * 16]);
    oa[0] = make_float4(av[0], av[1], av[2], av[3]);
    oa[1] = make_float4(av[4], av[5], av[6], av[7]);
    oa[2] = make_float4(av[8], av[9], av[10], av[11]);
    oa[3] = make_float4(av[12], av[13], av[14], av[15]);
    ob[0] = make_float4(bv[0], bv[1], bv[2], bv[3]);
    ob[1] = make_float4(bv[4], bv[5], bv[6], bv[7]);
    ob[2] = make_float4(bv[8], bv[9], bv[10], bv[11]);
    ob[3] = make_float4(bv[12], bv[13], bv[14], bv[15]);
}

// ---------------- K7: edge MLP output ----------------
__global__ void k_edge_out(const int* __restrict__ ei, const float* __restrict__ eattr,
                           const float* __restrict__ we1, const float* __restrict__ we2,
                           const float* __restrict__ be2, float* __restrict__ out) {
    __shared__ float sWc[5 * 16];  // we1 rows 32..36
    __shared__ float sW2[16];
    __shared__ float sb2;
    int t = threadIdx.x;
    for (int j = t; j < 80; j += blockDim.x) sWc[j] = we1[32 * 16 + j];
    if (t < 16) sW2[t] = we2[t];
    if (t == 0) sb2 = be2[0];
    __syncthreads();

    int e = blockIdx.x * blockDim.x + t;
    if (e >= NE) return;
    int s = ei[e];
    int d = ei[NE + e];

    const float4* pa = reinterpret_cast<const float4*>(g_A + s * 16);
    const float4* pb = reinterpret_cast<const float4*>(g_B + d * 16);
    float h[16];
#pragma unroll
    for (int i = 0; i < 4; i++) {
        float4 a = pa[i], b = pb[i];
        h[4 * i + 0] = a.x + b.x;
        h[4 * i + 1] = a.y + b.y;
        h[4 * i + 2] = a.z + b.z;
        h[4 * i + 3] = a.w + b.w;
    }
    const float* ep = eattr + (long)e * EF;
#pragma unroll
    for (int j = 0; j < EF; j++) {
        float ea = ep[j];
#pragma unroll
        for (int k = 0; k < 16; k++) h[k] += ea * sWc[j * 16 + k];
    }
    float acc = sb2;
#pragma unroll
    for (int k = 0; k < 16; k++) acc += fmaxf(h[k], 0.f) * sW2[k];
    out[e] = acc;
}

extern "C" void kernel_launch(void* const* d_in, const int* in_sizes, int n_in,
                              void* d_out, int out_size) {
    const int*   seq   = (const int*)d_in[0];
    const float* xcov  = (const float*)d_in[1];
    const int*   ei    = (const int*)d_in[2];
    const float* eattr = (const float*)d_in[3];
    const int*   batch = (const int*)d_in[4];
    const float* embed = (const float*)d_in[5];
    const float* w1    = (const float*)d_in[6];
    const float* b1    = (const float*)d_in[7];
    const float* w2    = (const float*)d_in[8];
    const float* b2    = (const float*)d_in[9];
    const float* we1   = (const float*)d_in[10];
    const float* be1   = (const float*)d_in[11];
    const float* we2   = (const float*)d_in[12];
    const float* be2   = (const float*)d_in[13];
    float* out = (float*)d_out;

    const int TB = 256;
    const int nb_e = (NE + TB - 1) / TB;
    const int nb_n = (NND + TB - 1) / TB;

    k_zero<<<2048, TB>>>();
    k_degree<<<nb_e, TB>>>(ei, batch);
    k_encode<<<nb_n, TB>>>(seq, xcov, embed, w1, b1);
    k_aggregate<0><<<nb_e, TB>>>(ei, batch);
    k_finalize1<<<nb_n, TB>>>(w2, b2);
    k_aggregate<1><<<nb_e, TB>>>(ei, batch);
    k_finalize2<<<nb_n, TB>>>(we1, be1);
    k_edge_out<<<nb_e, TB>>>(ei, eattr, we1, we2, be2, out);
}

// round 2
// speedup vs baseline: 1.0941x; 1.0941x over previous
#include <cuda_runtime.h>
#include <math.h>

#define NND 100000
#define NE  3200000
#define LTOK 64
#define HID 16
#define EF  5

// ---- scratch (device globals; no allocation allowed) ----
__device__ float g_dinv[NND];
__device__ int   g_deg[NND];
__device__ float g_Ms1[NND * HID];   // dinv * (X@w1+b1)
__device__ float g_Ms2[NND * HID];   // dinv * (H1@w2+b2)
__device__ float g_agg1[NND * HID];
__device__ float g_agg2[NND * HID];
__device__ float g_A[NND * HID];
__device__ float g_B[NND * HID];
__device__ int2  g_ve[NE];           // compacted valid edges (s, d)
__device__ int   g_vcnt;

__device__ __forceinline__ void red_add_v4(float* p, float4 v) {
    asm volatile("red.global.add.v4.f32 [%0], {%1, %2, %3, %4};"
                 :: "l"(p), "f"(v.x), "f"(v.y), "f"(v.z), "f"(v.w) : "memory");
}

// ---------------- K0: zero degree + counter ----------------
__global__ void k_zero_small() {
    int i = blockIdx.x * blockDim.x + threadIdx.x;
    if (i < NND) g_deg[i] = 0;
    if (i == 0) g_vcnt = 0;
}

// ---------------- K1: degree + valid-edge compaction ----------------
__global__ void k_deg_compact(const int* __restrict__ ei, const int* __restrict__ batch) {
    int e = blockIdx.x * blockDim.x + threadIdx.x;
    bool valid = false;
    int s = 0, d = 0;
    if (e < NE) {
        s = ei[e];
        d = ei[NE + e];
        valid = (batch[s] == batch[d]);
    }
    unsigned m = __ballot_sync(0xffffffffu, valid);
    if (valid) {
        atomicAdd(&g_deg[s], 1);
        int lane = threadIdx.x & 31;
        int leader = __ffs(m) - 1;
        int base = 0;
        if (lane == leader) base = atomicAdd(&g_vcnt, __popc(m));
        base = __shfl_sync(m, base, leader);
        int rank = __popc(m & ((1u << lane) - 1u));
        g_ve[base + rank] = make_int2(s, d);
    }
}

// ---------------- K2: encode nodes + dinv + Ms1 = dinv*(X@w1+b1); zero agg1 ----------------
__global__ void k_encode(const int* __restrict__ seq, const float* __restrict__ xcov,
                         const float* __restrict__ embed, const float* __restrict__ w1,
                         const float* __restrict__ b1) {
    __shared__ float s_emb[6 * 16];
    __shared__ float s_w1[17 * 16];
    __shared__ float s_b1[16];
    int t = threadIdx.x;
    for (int j = t; j < 96; j += blockDim.x) s_emb[j] = embed[j];
    for (int j = t; j < 272; j += blockDim.x) s_w1[j] = w1[j];
    if (t < 16) s_b1[t] = b1[t];
    __syncthreads();

    int n = blockIdx.x * blockDim.x + t;
    if (n >= NND) return;

    float dinv = rsqrtf((float)g_deg[n] + 1.0f + 1e-8f);
    g_dinv[n] = dinv;

    // zero agg1 row
    float4 z = make_float4(0.f, 0.f, 0.f, 0.f);
    float4* zp = reinterpret_cast<float4*>(&g_agg1[n * 16]);
    zp[0] = z; zp[1] = z; zp[2] = z; zp[3] = z;

    float acc[16];
#pragma unroll
    for (int k = 0; k < 16; k++) acc[k] = 0.f;
    int cnt = 0;

    const int4* tp = reinterpret_cast<const int4*>(seq + (long)n * LTOK);
#pragma unroll
    for (int i = 0; i < 16; i++) {
        int4 v = tp[i];
        int tok[4] = {v.x, v.y, v.z, v.w};
#pragma unroll
        for (int j = 0; j < 4; j++) {
            int tk = tok[j];
            cnt += (tk != 0);
            const float* er = &s_emb[tk * 16];  // row 0 all-zero (padding_idx)
#pragma unroll
            for (int k = 0; k < 16; k++) acc[k] += er[k];
        }
    }
    float inv = 1.0f / fmaxf((float)cnt, 1.0f);

    float x[17];
#pragma unroll
    for (int k = 0; k < 16; k++) x[k] = acc[k] * inv;
    x[16] = xcov[n];

    float m[16];
#pragma unroll
    for (int k = 0; k < 16; k++) {
        float s = s_b1[k];
#pragma unroll
        for (int j = 0; j < 17; j++) s += x[j] * s_w1[j * 16 + k];
        m[k] = s * dinv;  // pre-scale by dinv
    }
    float4* mp = reinterpret_cast<float4*>(&g_Ms1[n * 16]);
    mp[0] = make_float4(m[0], m[1], m[2], m[3]);
    mp[1] = make_float4(m[4], m[5], m[6], m[7]);
    mp[2] = make_float4(m[8], m[9], m[10], m[11]);
    mp[3] = make_float4(m[12], m[13], m[14], m[15]);
}

// ---------------- K3/K5: aggregation over compacted valid edges ----------------
template <int LAYER>
__global__ void k_aggregate() {
    int cnt = g_vcnt;
    int stride = gridDim.x * blockDim.x;
    const float* Ms = (LAYER == 0) ? g_Ms1 : g_Ms2;
    float* agg = (LAYER == 0) ? g_agg1 : g_agg2;
    for (int i = blockIdx.x * blockDim.x + threadIdx.x; i < cnt; i += stride) {
        int2 sd = g_ve[i];
        const float4* mp = reinterpret_cast<const float4*>(Ms + sd.y * 16);
        float* ap = agg + sd.x * 16;
#pragma unroll
        for (int j = 0; j < 4; j++) red_add_v4(ap + 4 * j, mp[j]);
    }
}

// ---------------- K4: H1 = relu(dinv*agg1 + dinv*Ms1); Ms2 = dinv*(H1@w2+b2); zero agg2 ----------------
__global__ void k_finalize1(const float* __restrict__ w2, const float* __restrict__ b2) {
    __shared__ float sW[16 * 16];
    __shared__ float sb[16];
    int t = threadIdx.x;
    for (int j = t; j < 256; j += blockDim.x) sW[j] = w2[j];
    if (t < 16) sb[t] = b2[t];
    __syncthreads();

    int n = blockIdx.x * blockDim.x + t;
    if (n >= NND) return;
    float dinv = g_dinv[n];

    float4 z = make_float4(0.f, 0.f, 0.f, 0.f);
    float4* zp = reinterpret_cast<float4*>(&g_agg2[n * 16]);
    zp[0] = z; zp[1] = z; zp[2] = z; zp[3] = z;

    const float4* ap = reinterpret_cast<const float4*>(g_agg1 + n * 16);
    const float4* mp = reinterpret_cast<const float4*>(g_Ms1 + n * 16);
    float h[16];
#pragma unroll
    for (int i = 0; i < 4; i++) {
        float4 a = ap[i], m = mp[i];
        h[4 * i + 0] = fmaxf(dinv * (a.x + m.x), 0.f);
        h[4 * i + 1] = fmaxf(dinv * (a.y + m.y), 0.f);
        h[4 * i + 2] = fmaxf(dinv * (a.z + m.z), 0.f);
        h[4 * i + 3] = fmaxf(dinv * (a.w + m.w), 0.f);
    }
    float m2[16];
#pragma unroll
    for (int k = 0; k < 16; k++) {
        float s = sb[k];
#pragma unroll
        for (int j = 0; j < 16; j++) s += h[j] * sW[j * 16 + k];
        m2[k] = s * dinv;  // pre-scale
    }
    float4* op = reinterpret_cast<float4*>(&g_Ms2[n * 16]);
    op[0] = make_float4(m2[0], m2[1], m2[2], m2[3]);
    op[1] = make_float4(m2[4], m2[5], m2[6], m2[7]);
    op[2] = make_float4(m2[8], m2[9], m2[10], m2[11]);
    op[3] = make_float4(m2[12], m2[13], m2[14], m2[15]);
}

// ---------------- K6: H2 -> A = H2@we1[0:16]+be1, B = H2@we1[16:32] ----------------
__global__ void k_finalize2(const float* __restrict__ we1, const float* __restrict__ be1) {
    __shared__ float sW[32 * 16];
    __shared__ float sb[16];
    int t = threadIdx.x;
    for (int j = t; j < 512; j += blockDim.x) sW[j] = we1[j];
    if (t < 16) sb[t] = be1[t];
    __syncthreads();

    int n = blockIdx.x * blockDim.x + t;
    if (n >= NND) return;
    float dinv = g_dinv[n];
    const float4* ap = reinterpret_cast<const float4*>(g_agg2 + n * 16);
    const float4* mp = reinterpret_cast<const float4*>(g_Ms2 + n * 16);
    float h[16];
#pragma unroll
    for (int i = 0; i < 4; i++) {
        float4 a = ap[i], m = mp[i];
        h[4 * i + 0] = fmaxf(dinv * (a.x + m.x), 0.f);
        h[4 * i + 1] = fmaxf(dinv * (a.y + m.y), 0.f);
        h[4 * i + 2] = fmaxf(dinv * (a.z + m.z), 0.f);
        h[4 * i + 3] = fmaxf(dinv * (a.w + m.w), 0.f);
    }
    float av[16], bv[16];
#pragma unroll
    for (int k = 0; k < 16; k++) {
        float sa = sb[k];
        float sbv = 0.f;
#pragma unroll
        for (int j = 0; j < 16; j++) {
            sa  += h[j] * sW[j * 16 + k];
            sbv += h[j] * sW[(16 + j) * 16 + k];
        }
        av[k] = sa; bv[k] = sbv;
    }
    float4* oa = reinterpret_cast<float4*>(&g_A[n * 16]);
    float4* ob = reinterpret_cast<float4*>(&g_B[n * 16]);
    oa[0] = make_float4(av[0], av[1], av[2], av[3]);
    oa[1] = make_float4(av[4], av[5], av[6], av[7]);
    oa[2] = make_float4(av[8], av[9], av[10], av[11]);
    oa[3] = make_float4(av[12], av[13], av[14], av[15]);
    ob[0] = make_float4(bv[0], bv[1], bv[2], bv[3]);
    ob[1] = make_float4(bv[4], bv[5], bv[6], bv[7]);
    ob[2] = make_float4(bv[8], bv[9], bv[10], bv[11]);
    ob[3] = make_float4(bv[12], bv[13], bv[14], bv[15]);
}

// ---------------- K7: edge MLP output ----------------
__global__ void k_edge_out(const int* __restrict__ ei, const float* __restrict__ eattr,
                           const float* __restrict__ we1, const float* __restrict__ we2,
                           const float* __restrict__ be2, float* __restrict__ out) {
    __shared__ float sWc[5 * 16];  // we1 rows 32..36
    __shared__ float sW2[16];
    __shared__ float sb2;
    int t = threadIdx.x;
    for (int j = t; j < 80; j += blockDim.x) sWc[j] = we1[32 * 16 + j];
    if (t < 16) sW2[t] = we2[t];
    if (t == 0) sb2 = be2[0];
    __syncthreads();

    int e = blockIdx.x * blockDim.x + t;
    if (e >= NE) return;
    int s = ei[e];
    int d = ei[NE + e];

    const float4* pa = reinterpret_cast<const float4*>(g_A + s * 16);
    const float4* pb = reinterpret_cast<const float4*>(g_B + d * 16);
    float h[16];
#pragma unroll
    for (int i = 0; i < 4; i++) {
        float4 a = pa[i], b = pb[i];
        h[4 * i + 0] = a.x + b.x;
        h[4 * i + 1] = a.y + b.y;
        h[4 * i + 2] = a.z + b.z;
        h[4 * i + 3] = a.w + b.w;
    }
    const float* ep = eattr + (long)e * EF;
#pragma unroll
    for (int j = 0; j < EF; j++) {
        float ea = ep[j];
#pragma unroll
        for (int k = 0; k < 16; k++) h[k] += ea * sWc[j * 16 + k];
    }
    float acc = sb2;
#pragma unroll
    for (int k = 0; k < 16; k++) acc += fmaxf(h[k], 0.f) * sW2[k];
    out[e] = acc;
}

extern "C" void kernel_launch(void* const* d_in, const int* in_sizes, int n_in,
                              void* d_out, int out_size) {
    const int*   seq   = (const int*)d_in[0];
    const float* xcov  = (const float*)d_in[1];
    const int*   ei    = (const int*)d_in[2];
    const float* eattr = (const float*)d_in[3];
    const int*   batch = (const int*)d_in[4];
    const float* embed = (const float*)d_in[5];
    const float* w1    = (const float*)d_in[6];
    const float* b1    = (const float*)d_in[7];
    const float* w2    = (const float*)d_in[8];
    const float* b2    = (const float*)d_in[9];
    const float* we1   = (const float*)d_in[10];
    const float* be1   = (const float*)d_in[11];
    const float* we2   = (const float*)d_in[12];
    const float* be2   = (const float*)d_in[13];
    float* out = (float*)d_out;

    const int TB = 256;
    const int nb_e = (NE + TB - 1) / TB;
    const int nb_n = (NND + TB - 1) / TB;

    k_zero_small<<<nb_n, TB>>>();
    k_deg_compact<<<nb_e, TB>>>(ei, batch);
    k_encode<<<nb_n, TB>>>(seq, xcov, embed, w1, b1);
    k_aggregate<0><<<512, TB>>>();
    k_finalize1<<<nb_n, TB>>>(w2, b2);
    k_aggregate<1><<<512, TB>>>();
    k_finalize2<<<nb_n, TB>>>(we1, be1);
    k_edge_out<<<nb_e, TB>>>(ei, eattr, we1, we2, be2, out);
}

// round 3
// speedup vs baseline: 1.7108x; 1.5636x over previous
#include <cuda_runtime.h>
#include <cuda_fp16.h>
#include <math.h>

#define NND 100000
#define NE  3200000
#define LTOK 64
#define HID 16
#define EF  5

// ---- scratch (device globals; no allocation allowed) ----
__device__ float g_dinv[NND];
__device__ int   g_deg[NND];
__device__ float g_Ms1[NND * HID];   // dinv * (X@w1+b1)
__device__ float g_Ms2[NND * HID];   // dinv * (H1@w2+b2)
__device__ float g_agg1[NND * HID];
__device__ float g_agg2[NND * HID];
__device__ uint4 g_Ah4[NND * 2];     // A row = 16 half = 32B = 2x uint4
__device__ uint4 g_Bh4[NND * 2];     // B row = 16 half
__device__ int2  g_ve[NE];           // compacted valid edges (s, d)
__device__ int   g_vcnt;

__device__ __forceinline__ void red_add_v4(float* p, float4 v) {
    asm volatile("red.global.add.v4.f32 [%0], {%1, %2, %3, %4};"
                 :: "l"(p), "f"(v.x), "f"(v.y), "f"(v.z), "f"(v.w) : "memory");
}

// ---------------- K0: zero degree + counter ----------------
__global__ void k_zero_small() {
    int i = blockIdx.x * blockDim.x + threadIdx.x;
    if (i < NND) g_deg[i] = 0;
    if (i == 0) g_vcnt = 0;
}

// ---------------- K1: degree + valid-edge compaction (4 edges/thread) ----------------
__global__ void k_deg_compact(const int* __restrict__ ei, const int* __restrict__ batch) {
    int t = blockIdx.x * blockDim.x + threadIdx.x;
    int base_e = t * 4;                     // NE % (4*256) == 0, all full
    int4 s4 = *reinterpret_cast<const int4*>(ei + base_e);
    int4 d4 = *reinterpret_cast<const int4*>(ei + NE + base_e);
    int sv[4] = {s4.x, s4.y, s4.z, s4.w};
    int dv[4] = {d4.x, d4.y, d4.z, d4.w};
    bool v[4];
    int cnt = 0;
#pragma unroll
    for (int j = 0; j < 4; j++) {
        v[j] = (__ldg(batch + sv[j]) == __ldg(batch + dv[j]));
        if (v[j]) { atomicAdd(&g_deg[sv[j]], 1); cnt++; }
    }
    // warp-aggregated append
    int lane = threadIdx.x & 31;
    int incl = cnt;
#pragma unroll
    for (int off = 1; off < 32; off <<= 1) {
        int nv = __shfl_up_sync(0xffffffffu, incl, off);
        if (lane >= off) incl += nv;
    }
    int total = __shfl_sync(0xffffffffu, incl, 31);
    int basew = 0;
    if (lane == 31 && total > 0) basew = atomicAdd(&g_vcnt, total);
    basew = __shfl_sync(0xffffffffu, basew, 31);
    int pos = basew + incl - cnt;
#pragma unroll
    for (int j = 0; j < 4; j++) {
        if (v[j]) g_ve[pos++] = make_int2(sv[j], dv[j]);
    }
}

// ---------------- K2: encode nodes (token histogram) + dinv + Ms1; zero agg1 ----------------
__global__ void k_encode(const int* __restrict__ seq, const float* __restrict__ xcov,
                         const float* __restrict__ embed, const float* __restrict__ w1,
                         const float* __restrict__ b1) {
    __shared__ float s_emb[6 * 16];
    __shared__ float s_w1[17 * 16];
    __shared__ float s_b1[16];
    int t = threadIdx.x;
    for (int j = t; j < 96; j += blockDim.x) s_emb[j] = embed[j];
    for (int j = t; j < 272; j += blockDim.x) s_w1[j] = w1[j];
    if (t < 16) s_b1[t] = b1[t];
    __syncthreads();

    int n = blockIdx.x * blockDim.x + t;
    if (n >= NND) return;

    float dinv = rsqrtf((float)g_deg[n] + 1.0f + 1e-8f);
    g_dinv[n] = dinv;

    // zero agg1 row
    float4 z = make_float4(0.f, 0.f, 0.f, 0.f);
    float4* zp = reinterpret_cast<float4*>(&g_agg1[n * 16]);
    zp[0] = z; zp[1] = z; zp[2] = z; zp[3] = z;

    // token histogram (vocab = 6, row 0 is padding/all-zero)
    int c1 = 0, c2 = 0, c3 = 0, c4 = 0, c5 = 0;
    const int4* tp = reinterpret_cast<const int4*>(seq + (long)n * LTOK);
#pragma unroll
    for (int i = 0; i < 16; i++) {
        int4 v = tp[i];
        int tok[4] = {v.x, v.y, v.z, v.w};
#pragma unroll
        for (int j = 0; j < 4; j++) {
            int tk = tok[j];
            c1 += (tk == 1); c2 += (tk == 2); c3 += (tk == 3);
            c4 += (tk == 4); c5 += (tk == 5);
        }
    }
    int nz = c1 + c2 + c3 + c4 + c5;
    float inv = 1.0f / fmaxf((float)nz, 1.0f);
    float f1 = c1 * inv, f2 = c2 * inv, f3 = c3 * inv, f4 = c4 * inv, f5 = c5 * inv;

    float x[17];
#pragma unroll
    for (int k = 0; k < 16; k++) {
        x[k] = f1 * s_emb[16 + k] + f2 * s_emb[32 + k] + f3 * s_emb[48 + k]
             + f4 * s_emb[64 + k] + f5 * s_emb[80 + k];
    }
    x[16] = xcov[n];

    float m[16];
#pragma unroll
    for (int k = 0; k < 16; k++) {
        float s = s_b1[k];
#pragma unroll
        for (int j = 0; j < 17; j++) s += x[j] * s_w1[j * 16 + k];
        m[k] = s * dinv;  // pre-scale by dinv
    }
    float4* mp = reinterpret_cast<float4*>(&g_Ms1[n * 16]);
    mp[0] = make_float4(m[0], m[1], m[2], m[3]);
    mp[1] = make_float4(m[4], m[5], m[6], m[7]);
    mp[2] = make_float4(m[8], m[9], m[10], m[11]);
    mp[3] = make_float4(m[12], m[13], m[14], m[15]);
}

// ---------------- K3/K5: aggregation over compacted valid edges ----------------
template <int LAYER>
__global__ void k_aggregate() {
    int cnt = g_vcnt;
    int stride = gridDim.x * blockDim.x;
    const float* Ms = (LAYER == 0) ? g_Ms1 : g_Ms2;
    float* agg = (LAYER == 0) ? g_agg1 : g_agg2;
    for (int i = blockIdx.x * blockDim.x + threadIdx.x; i < cnt; i += stride) {
        int2 sd = g_ve[i];
        const float4* mp = reinterpret_cast<const float4*>(Ms + sd.y * 16);
        float* ap = agg + sd.x * 16;
#pragma unroll
        for (int j = 0; j < 4; j++) red_add_v4(ap + 4 * j, mp[j]);
    }
}

// ---------------- K4: H1 = relu(dinv*(agg1+Ms1)); Ms2 = dinv*(H1@w2+b2); zero agg2 ----------------
__global__ void k_finalize1(const float* __restrict__ w2, const float* __restrict__ b2) {
    __shared__ float sW[16 * 16];
    __shared__ float sb[16];
    int t = threadIdx.x;
    for (int j = t; j < 256; j += blockDim.x) sW[j] = w2[j];
    if (t < 16) sb[t] = b2[t];
    __syncthreads();

    int n = blockIdx.x * blockDim.x + t;
    if (n >= NND) return;
    float dinv = g_dinv[n];

    float4 z = make_float4(0.f, 0.f, 0.f, 0.f);
    float4* zp = reinterpret_cast<float4*>(&g_agg2[n * 16]);
    zp[0] = z; zp[1] = z; zp[2] = z; zp[3] = z;

    const float4* ap = reinterpret_cast<const float4*>(g_agg1 + n * 16);
    const float4* mp = reinterpret_cast<const float4*>(g_Ms1 + n * 16);
    float h[16];
#pragma unroll
    for (int i = 0; i < 4; i++) {
        float4 a = ap[i], m = mp[i];
        h[4 * i + 0] = fmaxf(dinv * (a.x + m.x), 0.f);
        h[4 * i + 1] = fmaxf(dinv * (a.y + m.y), 0.f);
        h[4 * i + 2] = fmaxf(dinv * (a.z + m.z), 0.f);
        h[4 * i + 3] = fmaxf(dinv * (a.w + m.w), 0.f);
    }
    float m2[16];
#pragma unroll
    for (int k = 0; k < 16; k++) {
        float s = sb[k];
#pragma unroll
        for (int j = 0; j < 16; j++) s += h[j] * sW[j * 16 + k];
        m2[k] = s * dinv;  // pre-scale
    }
    float4* op = reinterpret_cast<float4*>(&g_Ms2[n * 16]);
    op[0] = make_float4(m2[0], m2[1], m2[2], m2[3]);
    op[1] = make_float4(m2[4], m2[5], m2[6], m2[7]);
    op[2] = make_float4(m2[8], m2[9], m2[10], m2[11]);
    op[3] = make_float4(m2[12], m2[13], m2[14], m2[15]);
}

// ---------------- K6: H2 -> A,B stored fp16 ----------------
__global__ void k_finalize2(const float* __restrict__ we1, const float* __restrict__ be1) {
    __shared__ float sW[32 * 16];
    __shared__ float sb[16];
    int t = threadIdx.x;
    for (int j = t; j < 512; j += blockDim.x) sW[j] = we1[j];
    if (t < 16) sb[t] = be1[t];
    __syncthreads();

    int n = blockIdx.x * blockDim.x + t;
    if (n >= NND) return;
    float dinv = g_dinv[n];
    const float4* ap = reinterpret_cast<const float4*>(g_agg2 + n * 16);
    const float4* mp = reinterpret_cast<const float4*>(g_Ms2 + n * 16);
    float h[16];
#pragma unroll
    for (int i = 0; i < 4; i++) {
        float4 a = ap[i], m = mp[i];
        h[4 * i + 0] = fmaxf(dinv * (a.x + m.x), 0.f);
        h[4 * i + 1] = fmaxf(dinv * (a.y + m.y), 0.f);
        h[4 * i + 2] = fmaxf(dinv * (a.z + m.z), 0.f);
        h[4 * i + 3] = fmaxf(dinv * (a.w + m.w), 0.f);
    }
    float av[16], bv[16];
#pragma unroll
    for (int k = 0; k < 16; k++) {
        float sa = sb[k];
        float sbv = 0.f;
#pragma unroll
        for (int j = 0; j < 16; j++) {
            sa  += h[j] * sW[j * 16 + k];
            sbv += h[j] * sW[(16 + j) * 16 + k];
        }
        av[k] = sa; bv[k] = sbv;
    }
    unsigned wa[8], wb[8];
#pragma unroll
    for (int i = 0; i < 8; i++) {
        __half2 pa = __floats2half2_rn(av[2 * i], av[2 * i + 1]);
        __half2 pb = __floats2half2_rn(bv[2 * i], bv[2 * i + 1]);
        wa[i] = *reinterpret_cast<unsigned*>(&pa);
        wb[i] = *reinterpret_cast<unsigned*>(&pb);
    }
    g_Ah4[2 * n + 0] = make_uint4(wa[0], wa[1], wa[2], wa[3]);
    g_Ah4[2 * n + 1] = make_uint4(wa[4], wa[5], wa[6], wa[7]);
    g_Bh4[2 * n + 0] = make_uint4(wb[0], wb[1], wb[2], wb[3]);
    g_Bh4[2 * n + 1] = make_uint4(wb[4], wb[5], wb[6], wb[7]);
}

// ---------------- K7: edge MLP output (4 edges/thread) ----------------
__global__ void k_edge_out(const int* __restrict__ ei, const float* __restrict__ eattr,
                           const float* __restrict__ we1, const float* __restrict__ we2,
                           const float* __restrict__ be2, float* __restrict__ out) {
    __shared__ float sWc[5 * 16];  // we1 rows 32..36
    __shared__ float sW2[16];
    __shared__ float sb2;
    int t = threadIdx.x;
    for (int j = t; j < 80; j += blockDim.x) sWc[j] = we1[32 * 16 + j];
    if (t < 16) sW2[t] = we2[t];
    if (t == 0) sb2 = be2[0];
    __syncthreads();

    int gt = blockIdx.x * blockDim.x + t;
    int base_e = gt * 4;                    // NE % (4*256) == 0
    int4 s4 = *reinterpret_cast<const int4*>(ei + base_e);
    int4 d4 = *reinterpret_cast<const int4*>(ei + NE + base_e);
    int sv[4] = {s4.x, s4.y, s4.z, s4.w};
    int dv[4] = {d4.x, d4.y, d4.z, d4.w};

    // 20 edge-attr floats for 4 edges; 16B-aligned
    float ea[20];
    const float4* ep = reinterpret_cast<const float4*>(eattr + (long)base_e * EF);
#pragma unroll
    for (int i = 0; i < 5; i++) {
        float4 v = ep[i];
        ea[4 * i + 0] = v.x; ea[4 * i + 1] = v.y; ea[4 * i + 2] = v.z; ea[4 * i + 3] = v.w;
    }

    float res[4];
#pragma unroll
    for (int j = 0; j < 4; j++) {
        uint4 a0 = g_Ah4[2 * sv[j] + 0];
        uint4 a1 = g_Ah4[2 * sv[j] + 1];
        uint4 b0 = g_Bh4[2 * dv[j] + 0];
        uint4 b1 = g_Bh4[2 * dv[j] + 1];
        unsigned aw[8] = {a0.x, a0.y, a0.z, a0.w, a1.x, a1.y, a1.z, a1.w};
        unsigned bw[8] = {b0.x, b0.y, b0.z, b0.w, b1.x, b1.y, b1.z, b1.w};
        float h[16];
#pragma unroll
        for (int i = 0; i < 8; i++) {
            float2 fa = __half22float2(*reinterpret_cast<__half2*>(&aw[i]));
            float2 fb = __half22float2(*reinterpret_cast<__half2*>(&bw[i]));
            h[2 * i + 0] = fa.x + fb.x;
            h[2 * i + 1] = fa.y + fb.y;
        }
#pragma unroll
        for (int q = 0; q < EF; q++) {
            float eav = ea[5 * j + q];
#pragma unroll
            for (int k = 0; k < 16; k++) h[k] += eav * sWc[q * 16 + k];
        }
        float acc = sb2;
#pragma unroll
        for (int k = 0; k < 16; k++) acc += fmaxf(h[k], 0.f) * sW2[k];
        res[j] = acc;
    }
    *reinterpret_cast<float4*>(out + base_e) = make_float4(res[0], res[1], res[2], res[3]);
}

extern "C" void kernel_launch(void* const* d_in, const int* in_sizes, int n_in,
                              void* d_out, int out_size) {
    const int*   seq   = (const int*)d_in[0];
    const float* xcov  = (const float*)d_in[1];
    const int*   ei    = (const int*)d_in[2];
    const float* eattr = (const float*)d_in[3];
    const int*   batch = (const int*)d_in[4];
    const float* embed = (const float*)d_in[5];
    const float* w1    = (const float*)d_in[6];
    const float* b1    = (const float*)d_in[7];
    const float* w2    = (const float*)d_in[8];
    const float* b2    = (const float*)d_in[9];
    const float* we1   = (const float*)d_in[10];
    const float* be1   = (const float*)d_in[11];
    const float* we2   = (const float*)d_in[12];
    const float* be2   = (const float*)d_in[13];
    float* out = (float*)d_out;

    const int TB = 256;
    const int nb_e4 = NE / (TB * 4);        // 3125, exact
    const int nb_n = (NND + TB - 1) / TB;

    k_zero_small<<<nb_n, TB>>>();
    k_deg_compact<<<nb_e4, TB>>>(ei, batch);
    k_encode<<<nb_n, TB>>>(seq, xcov, embed, w1, b1);
    k_aggregate<0><<<512, TB>>>();
    k_finalize1<<<nb_n, TB>>>(w2, b2);
    k_aggregate<1><<<512, TB>>>();
    k_finalize2<<<nb_n, TB>>>(we1, be1);
    k_edge_out<<<nb_e4, TB>>>(ei, eattr, we1, we2, be2, out);
}

// round 4
// speedup vs baseline: 1.7658x; 1.0321x over previous
#include <cuda_runtime.h>
#include <cuda_fp16.h>
#include <math.h>

#define NND 100000
#define NE  3200000
#define LTOK 64
#define HID 16
#define EF  5

// ---- scratch (device globals; no allocation allowed) ----
__device__ float g_dinv[NND];
__device__ int   g_deg[NND];
__device__ float g_Ms1[NND * HID];   // dinv * (X@w1+b1)
__device__ float g_Ms2[NND * HID];   // dinv * (H1@w2+b2)
__device__ float g_agg1[NND * HID];
__device__ float g_agg2[NND * HID];
__device__ uint4 g_Ah4[NND * 2];     // A row = 16 half = 32B
__device__ uint4 g_Bh4[NND * 2];     // B row = 16 half
__device__ __align__(16) int2 g_ve[NE + 2];  // compacted valid edges (s, d)
__device__ int   g_vcnt;

__device__ __forceinline__ void red_add_v4(float* p, float4 v) {
    asm volatile("red.global.add.v4.f32 [%0], {%1, %2, %3, %4};"
                 :: "l"(p), "f"(v.x), "f"(v.y), "f"(v.z), "f"(v.w) : "memory");
}

// ---------------- K0: zero degree + counter ----------------
__global__ void k_zero_small() {
    int i = blockIdx.x * blockDim.x + threadIdx.x;
    if (i < NND) g_deg[i] = 0;
    if (i == 0) g_vcnt = 0;
}

// ---------------- K1: degree + valid-edge compaction (8 edges/thread) ----------------
__global__ void k_deg_compact(const int* __restrict__ ei, const int* __restrict__ batch) {
    int t = blockIdx.x * blockDim.x + threadIdx.x;
    int base_e = t * 8;
    bool active = (base_e < NE);   // NE % 8 == 0: threads are all-or-nothing
    int sv[8], dv[8];
    bool v[8];
    int cnt = 0;
    if (active) {
        int4 sa = *reinterpret_cast<const int4*>(ei + base_e);
        int4 sb = *reinterpret_cast<const int4*>(ei + base_e + 4);
        int4 da = *reinterpret_cast<const int4*>(ei + NE + base_e);
        int4 db = *reinterpret_cast<const int4*>(ei + NE + base_e + 4);
        sv[0]=sa.x; sv[1]=sa.y; sv[2]=sa.z; sv[3]=sa.w;
        sv[4]=sb.x; sv[5]=sb.y; sv[6]=sb.z; sv[7]=sb.w;
        dv[0]=da.x; dv[1]=da.y; dv[2]=da.z; dv[3]=da.w;
        dv[4]=db.x; dv[5]=db.y; dv[6]=db.z; dv[7]=db.w;
        int bs[8], bd[8];
#pragma unroll
        for (int j = 0; j < 8; j++) { bs[j] = __ldg(batch + sv[j]); bd[j] = __ldg(batch + dv[j]); }
#pragma unroll
        for (int j = 0; j < 8; j++) {
            v[j] = (bs[j] == bd[j]);
            if (v[j]) { atomicAdd(&g_deg[sv[j]], 1); cnt++; }
        }
    } else {
#pragma unroll
        for (int j = 0; j < 8; j++) v[j] = false;
    }
    // warp-aggregated append
    int lane = threadIdx.x & 31;
    int incl = cnt;
#pragma unroll
    for (int off = 1; off < 32; off <<= 1) {
        int nv = __shfl_up_sync(0xffffffffu, incl, off);
        if (lane >= off) incl += nv;
    }
    int total = __shfl_sync(0xffffffffu, incl, 31);
    int basew = 0;
    if (lane == 31 && total > 0) basew = atomicAdd(&g_vcnt, total);
    basew = __shfl_sync(0xffffffffu, basew, 31);
    int pos = basew + incl - cnt;
#pragma unroll
    for (int j = 0; j < 8; j++) {
        if (v[j]) g_ve[pos++] = make_int2(sv[j], dv[j]);
    }
}

// ---------------- K2: encode nodes (token histogram) + dinv + Ms1; zero agg1 ----------------
__global__ void k_encode(const int* __restrict__ seq, const float* __restrict__ xcov,
                         const float* __restrict__ embed, const float* __restrict__ w1,
                         const float* __restrict__ b1) {
    __shared__ float s_emb[6 * 16];
    __shared__ float s_w1[17 * 16];
    __shared__ float s_b1[16];
    int t = threadIdx.x;
    for (int j = t; j < 96; j += blockDim.x) s_emb[j] = embed[j];
    for (int j = t; j < 272; j += blockDim.x) s_w1[j] = w1[j];
    if (t < 16) s_b1[t] = b1[t];
    __syncthreads();

    int n = blockIdx.x * blockDim.x + t;
    if (n >= NND) return;

    float dinv = rsqrtf((float)g_deg[n] + 1.0f + 1e-8f);
    g_dinv[n] = dinv;

    float4 z = make_float4(0.f, 0.f, 0.f, 0.f);
    float4* zp = reinterpret_cast<float4*>(&g_agg1[n * 16]);
    zp[0] = z; zp[1] = z; zp[2] = z; zp[3] = z;

    int c1 = 0, c2 = 0, c3 = 0, c4 = 0, c5 = 0;
    const int4* tp = reinterpret_cast<const int4*>(seq + (long)n * LTOK);
#pragma unroll
    for (int i = 0; i < 16; i++) {
        int4 v = tp[i];
        int tok[4] = {v.x, v.y, v.z, v.w};
#pragma unroll
        for (int j = 0; j < 4; j++) {
            int tk = tok[j];
            c1 += (tk == 1); c2 += (tk == 2); c3 += (tk == 3);
            c4 += (tk == 4); c5 += (tk == 5);
        }
    }
    int nz = c1 + c2 + c3 + c4 + c5;
    float inv = 1.0f / fmaxf((float)nz, 1.0f);
    float f1 = c1 * inv, f2 = c2 * inv, f3 = c3 * inv, f4 = c4 * inv, f5 = c5 * inv;

    float x[17];
#pragma unroll
    for (int k = 0; k < 16; k++) {
        x[k] = f1 * s_emb[16 + k] + f2 * s_emb[32 + k] + f3 * s_emb[48 + k]
             + f4 * s_emb[64 + k] + f5 * s_emb[80 + k];
    }
    x[16] = xcov[n];

    float m[16];
#pragma unroll
    for (int k = 0; k < 16; k++) {
        float s = s_b1[k];
#pragma unroll
        for (int j = 0; j < 17; j++) s += x[j] * s_w1[j * 16 + k];
        m[k] = s * dinv;  // pre-scale by dinv
    }
    float4* mp = reinterpret_cast<float4*>(&g_Ms1[n * 16]);
    mp[0] = make_float4(m[0], m[1], m[2], m[3]);
    mp[1] = make_float4(m[4], m[5], m[6], m[7]);
    mp[2] = make_float4(m[8], m[9], m[10], m[11]);
    mp[3] = make_float4(m[12], m[13], m[14], m[15]);
}

// ---------------- K3/K5: aggregation, 2 edges/thread ----------------
template <int LAYER>
__global__ void k_aggregate() {
    int cnt = g_vcnt;
    int npair = (cnt + 1) >> 1;
    int stride = gridDim.x * blockDim.x;
    const float* Ms = (LAYER == 0) ? g_Ms1 : g_Ms2;
    float* agg = (LAYER == 0) ? g_agg1 : g_agg2;
    for (int i = blockIdx.x * blockDim.x + threadIdx.x; i < npair; i += stride) {
        int4 e2 = *reinterpret_cast<const int4*>(&g_ve[2 * i]);
        const float4* mp0 = reinterpret_cast<const float4*>(Ms + e2.y * 16);
        const float4* mp1 = reinterpret_cast<const float4*>(Ms + e2.w * 16);
        float4 v0[4], v1[4];
        bool second = (2 * i + 1 < cnt);
#pragma unroll
        for (int j = 0; j < 4; j++) v0[j] = mp0[j];
        if (second) {
#pragma unroll
            for (int j = 0; j < 4; j++) v1[j] = mp1[j];
        }
        float* ap0 = agg + e2.x * 16;
#pragma unroll
        for (int j = 0; j < 4; j++) red_add_v4(ap0 + 4 * j, v0[j]);
        if (second) {
            float* ap1 = agg + e2.z * 16;
#pragma unroll
            for (int j = 0; j < 4; j++) red_add_v4(ap1 + 4 * j, v1[j]);
        }
    }
}

// ---------------- K4: H1 = relu(dinv*(agg1+Ms1)); Ms2 = dinv*(H1@w2+b2); zero agg2 ----------------
__global__ void k_finalize1(const float* __restrict__ w2, const float* __restrict__ b2) {
    __shared__ float sW[16 * 16];
    __shared__ float sb[16];
    int t = threadIdx.x;
    for (int j = t; j < 256; j += blockDim.x) sW[j] = w2[j];
    if (t < 16) sb[t] = b2[t];
    __syncthreads();

    int n = blockIdx.x * blockDim.x + t;
    if (n >= NND) return;
    float dinv = g_dinv[n];

    float4 z = make_float4(0.f, 0.f, 0.f, 0.f);
    float4* zp = reinterpret_cast<float4*>(&g_agg2[n * 16]);
    zp[0] = z; zp[1] = z; zp[2] = z; zp[3] = z;

    const float4* ap = reinterpret_cast<const float4*>(g_agg1 + n * 16);
    const float4* mp = reinterpret_cast<const float4*>(g_Ms1 + n * 16);
    float h[16];
#pragma unroll
    for (int i = 0; i < 4; i++) {
        float4 a = ap[i], m = mp[i];
        h[4 * i + 0] = fmaxf(dinv * (a.x + m.x), 0.f);
        h[4 * i + 1] = fmaxf(dinv * (a.y + m.y), 0.f);
        h[4 * i + 2] = fmaxf(dinv * (a.z + m.z), 0.f);
        h[4 * i + 3] = fmaxf(dinv * (a.w + m.w), 0.f);
    }
    float m2[16];
#pragma unroll
    for (int k = 0; k < 16; k++) {
        float s = sb[k];
#pragma unroll
        for (int j = 0; j < 16; j++) s += h[j] * sW[j * 16 + k];
        m2[k] = s * dinv;  // pre-scale
    }
    float4* op = reinterpret_cast<float4*>(&g_Ms2[n * 16]);
    op[0] = make_float4(m2[0], m2[1], m2[2], m2[3]);
    op[1] = make_float4(m2[4], m2[5], m2[6], m2[7]);
    op[2] = make_float4(m2[8], m2[9], m2[10], m2[11]);
    op[3] = make_float4(m2[12], m2[13], m2[14], m2[15]);
}

// ---------------- K6: H2 -> A,B stored fp16 ----------------
__global__ void k_finalize2(const float* __restrict__ we1, const float* __restrict__ be1) {
    __shared__ float sW[32 * 16];
    __shared__ float sb[16];
    int t = threadIdx.x;
    for (int j = t; j < 512; j += blockDim.x) sW[j] = we1[j];
    if (t < 16) sb[t] = be1[t];
    __syncthreads();

    int n = blockIdx.x * blockDim.x + t;
    if (n >= NND) return;
    float dinv = g_dinv[n];
    const float4* ap = reinterpret_cast<const float4*>(g_agg2 + n * 16);
    const float4* mp = reinterpret_cast<const float4*>(g_Ms2 + n * 16);
    float h[16];
#pragma unroll
    for (int i = 0; i < 4; i++) {
        float4 a = ap[i], m = mp[i];
        h[4 * i + 0] = fmaxf(dinv * (a.x + m.x), 0.f);
        h[4 * i + 1] = fmaxf(dinv * (a.y + m.y), 0.f);
        h[4 * i + 2] = fmaxf(dinv * (a.z + m.z), 0.f);
        h[4 * i + 3] = fmaxf(dinv * (a.w + m.w), 0.f);
    }
    float av[16], bv[16];
#pragma unroll
    for (int k = 0; k < 16; k++) {
        float sa = sb[k];
        float sbv = 0.f;
#pragma unroll
        for (int j = 0; j < 16; j++) {
            sa  += h[j] * sW[j * 16 + k];
            sbv += h[j] * sW[(16 + j) * 16 + k];
        }
        av[k] = sa; bv[k] = sbv;
    }
    unsigned wa[8], wb[8];
#pragma unroll
    for (int i = 0; i < 8; i++) {
        __half2 pa = __floats2half2_rn(av[2 * i], av[2 * i + 1]);
        __half2 pb = __floats2half2_rn(bv[2 * i], bv[2 * i + 1]);
        wa[i] = *reinterpret_cast<unsigned*>(&pa);
        wb[i] = *reinterpret_cast<unsigned*>(&pb);
    }
    g_Ah4[2 * n + 0] = make_uint4(wa[0], wa[1], wa[2], wa[3]);
    g_Ah4[2 * n + 1] = make_uint4(wa[4], wa[5], wa[6], wa[7]);
    g_Bh4[2 * n + 0] = make_uint4(wb[0], wb[1], wb[2], wb[3]);
    g_Bh4[2 * n + 1] = make_uint4(wb[4], wb[5], wb[6], wb[7]);
}

// ---------------- K7: edge MLP output (4 edges/thread, pipelined pairs) ----------------
__global__ void k_edge_out(const int* __restrict__ ei, const float* __restrict__ eattr,
                           const float* __restrict__ we1, const float* __restrict__ we2,
                           const float* __restrict__ be2, float* __restrict__ out) {
    __shared__ float sWc[5 * 16];  // we1 rows 32..36
    __shared__ float sW2[16];
    __shared__ float sb2;
    int t = threadIdx.x;
    for (int j = t; j < 80; j += blockDim.x) sWc[j] = we1[32 * 16 + j];
    if (t < 16) sW2[t] = we2[t];
    if (t == 0) sb2 = be2[0];
    __syncthreads();

    int gt = blockIdx.x * blockDim.x + t;
    int base_e = gt * 4;                    // NE % (4*256) == 0
    int4 s4 = *reinterpret_cast<const int4*>(ei + base_e);
    int4 d4 = *reinterpret_cast<const int4*>(ei + NE + base_e);
    int sv[4] = {s4.x, s4.y, s4.z, s4.w};
    int dv[4] = {d4.x, d4.y, d4.z, d4.w};

    // issue first pair's A/B gathers immediately
    uint4 pa[4], pb[4];
#pragma unroll
    for (int j = 0; j < 2; j++) {
        pa[2 * j + 0] = g_Ah4[2 * sv[j] + 0];
        pa[2 * j + 1] = g_Ah4[2 * sv[j] + 1];
        pb[2 * j + 0] = g_Bh4[2 * dv[j] + 0];
        pb[2 * j + 1] = g_Bh4[2 * dv[j] + 1];
    }
    // eattr stream load overlaps the gathers
    float ea[20];
    const float4* ep = reinterpret_cast<const float4*>(eattr + (long)base_e * EF);
#pragma unroll
    for (int i = 0; i < 5; i++) {
        float4 v = ep[i];
        ea[4 * i + 0] = v.x; ea[4 * i + 1] = v.y; ea[4 * i + 2] = v.z; ea[4 * i + 3] = v.w;
    }

    float res[4];
#pragma unroll
    for (int p = 0; p < 2; p++) {
        if (p == 1) {
            // issue second pair's gathers before computing first pair? compute order:
            // we compute pair 0 while pair 1 loads are in flight (loads issued here)
#pragma unroll
            for (int j = 2; j < 4; j++) {
                pa[2 * (j - 2) + 0] = g_Ah4[2 * sv[j] + 0];
                pa[2 * (j - 2) + 1] = g_Ah4[2 * sv[j] + 1];
                pb[2 * (j - 2) + 0] = g_Bh4[2 * dv[j] + 0];
                pb[2 * (j - 2) + 1] = g_Bh4[2 * dv[j] + 1];
            }
        }
#pragma unroll
        for (int q = 0; q < 2; q++) {
            int j = 2 * p + q;
            unsigned aw[8] = {pa[2*q].x, pa[2*q].y, pa[2*q].z, pa[2*q].w,
                              pa[2*q+1].x, pa[2*q+1].y, pa[2*q+1].z, pa[2*q+1].w};
            unsigned bw[8] = {pb[2*q].x, pb[2*q].y, pb[2*q].z, pb[2*q].w,
                              pb[2*q+1].x, pb[2*q+1].y, pb[2*q+1].z, pb[2*q+1].w};
            float h[16];
#pragma unroll
            for (int i = 0; i < 8; i++) {
                float2 fa = __half22float2(*reinterpret_cast<__half2*>(&aw[i]));
                float2 fb = __half22float2(*reinterpret_cast<__half2*>(&bw[i]));
                h[2 * i + 0] = fa.x + fb.x;
                h[2 * i + 1] = fa.y + fb.y;
            }
#pragma unroll
            for (int r = 0; r < EF; r++) {
                float eav = ea[5 * j + r];
#pragma unroll
                for (int k = 0; k < 16; k++) h[k] += eav * sWc[r * 16 + k];
            }
            float acc = sb2;
#pragma unroll
            for (int k = 0; k < 16; k++) acc += fmaxf(h[k], 0.f) * sW2[k];
            res[j] = acc;
        }
    }
    *reinterpret_cast<float4*>(out + base_e) = make_float4(res[0], res[1], res[2], res[3]);
}

extern "C" void kernel_launch(void* const* d_in, const int* in_sizes, int n_in,
                              void* d_out, int out_size) {
    const int*   seq   = (const int*)d_in[0];
    const float* xcov  = (const float*)d_in[1];
    const int*   ei    = (const int*)d_in[2];
    const float* eattr = (const float*)d_in[3];
    const int*   batch = (const int*)d_in[4];
    const float* embed = (const float*)d_in[5];
    const float* w1    = (const float*)d_in[6];
    const float* b1    = (const float*)d_in[7];
    const float* w2    = (const float*)d_in[8];
    const float* b2    = (const float*)d_in[9];
    const float* we1   = (const float*)d_in[10];
    const float* be1   = (const float*)d_in[11];
    const float* we2   = (const float*)d_in[12];
    const float* be2   = (const float*)d_in[13];
    float* out = (float*)d_out;

    const int TB = 256;
    const int nb_e4 = NE / (TB * 4);              // 3125
    const int nb_e8 = (NE / 8 + TB - 1) / TB;     // 1563
    const int nb_n = (NND + TB - 1) / TB;

    k_zero_small<<<nb_n, TB>>>();
    k_deg_compact<<<nb_e8, TB>>>(ei, batch);
    k_encode<<<nb_n, TB>>>(seq, xcov, embed, w1, b1);
    k_aggregate<0><<<192, TB>>>();
    k_finalize1<<<nb_n, TB>>>(w2, b2);
    k_aggregate<1><<<192, TB>>>();
    k_finalize2<<<nb_n, TB>>>(we1, be1);
    k_edge_out<<<nb_e4, TB>>>(ei, eattr, we1, we2, be2, out);
}

// round 5
// speedup vs baseline: 2.0201x; 1.1440x over previous
#include <cuda_runtime.h>
#include <cuda_fp16.h>
#include <math.h>

#define NND 100000
#define NE  3200000
#define LTOK 64
#define HID 16
#define EF  5

struct __align__(32) V8 { uint4 a, b; };
struct __align__(32) F8 { float4 a, b; };

// ---- scratch (device globals; no allocation allowed) ----
__device__ float g_dinv[NND];
__device__ int   g_deg[NND];
__device__ F8    g_Ms1[NND * 2];   // row n = [2n],[2n+1]; dinv*(X@w1+b1)
__device__ F8    g_Ms2[NND * 2];
__device__ F8    g_agg1[NND * 2];
__device__ F8    g_agg2[NND * 2];
__device__ V8    g_Ah[NND];        // A row = 16 half = 32B
__device__ V8    g_Bh[NND];
__device__ __align__(16) int2 g_ve[NE + 2];
__device__ int   g_vcnt;

__device__ __forceinline__ void red_add_v4(float* p, float4 v) {
    asm volatile("red.global.add.v4.f32 [%0], {%1, %2, %3, %4};"
                 :: "l"(p), "f"(v.x), "f"(v.y), "f"(v.z), "f"(v.w) : "memory");
}
__device__ __forceinline__ V8 ldg256u(const V8* p) {
    V8 r;
    asm volatile("ld.global.nc.v8.b32 {%0,%1,%2,%3,%4,%5,%6,%7}, [%8];"
        : "=r"(r.a.x), "=r"(r.a.y), "=r"(r.a.z), "=r"(r.a.w),
          "=r"(r.b.x), "=r"(r.b.y), "=r"(r.b.z), "=r"(r.b.w)
        : "l"(p));
    return r;
}
__device__ __forceinline__ F8 ldg256f(const F8* p) {
    F8 r;
    asm volatile("ld.global.nc.v8.f32 {%0,%1,%2,%3,%4,%5,%6,%7}, [%8];"
        : "=f"(r.a.x), "=f"(r.a.y), "=f"(r.a.z), "=f"(r.a.w),
          "=f"(r.b.x), "=f"(r.b.y), "=f"(r.b.z), "=f"(r.b.w)
        : "l"(p));
    return r;
}
__device__ __forceinline__ void stg256f(F8* p, const float* v) {
    asm volatile("st.global.v8.f32 [%0], {%1,%2,%3,%4,%5,%6,%7,%8};"
        :: "l"(p), "f"(v[0]), "f"(v[1]), "f"(v[2]), "f"(v[3]),
           "f"(v[4]), "f"(v[5]), "f"(v[6]), "f"(v[7]) : "memory");
}
__device__ __forceinline__ void stg256u(V8* p, const unsigned* v) {
    asm volatile("st.global.v8.b32 [%0], {%1,%2,%3,%4,%5,%6,%7,%8};"
        :: "l"(p), "r"(v[0]), "r"(v[1]), "r"(v[2]), "r"(v[3]),
           "r"(v[4]), "r"(v[5]), "r"(v[6]), "r"(v[7]) : "memory");
}

// ---------------- K0: zero degree + counter ----------------
__global__ void k_zero_small() {
    int i = blockIdx.x * blockDim.x + threadIdx.x;
    if (i < NND) g_deg[i] = 0;
    if (i == 0) g_vcnt = 0;
}

// ---------------- K1: degree + valid-edge compaction (8 edges/thread) ----------------
__global__ void k_deg_compact(const int* __restrict__ ei, const int* __restrict__ batch) {
    int t = blockIdx.x * blockDim.x + threadIdx.x;
    int base_e = t * 8;
    bool active = (base_e < NE);   // NE % 8 == 0
    int sv[8], dv[8];
    bool v[8];
    int cnt = 0;
    if (active) {
        V8 sa = ldg256u(reinterpret_cast<const V8*>(ei + base_e));
        V8 da = ldg256u(reinterpret_cast<const V8*>(ei + NE + base_e));
        sv[0]=sa.a.x; sv[1]=sa.a.y; sv[2]=sa.a.z; sv[3]=sa.a.w;
        sv[4]=sa.b.x; sv[5]=sa.b.y; sv[6]=sa.b.z; sv[7]=sa.b.w;
        dv[0]=da.a.x; dv[1]=da.a.y; dv[2]=da.a.z; dv[3]=da.a.w;
        dv[4]=da.b.x; dv[5]=da.b.y; dv[6]=da.b.z; dv[7]=da.b.w;
        int bs[8], bd[8];
#pragma unroll
        for (int j = 0; j < 8; j++) { bs[j] = __ldg(batch + sv[j]); bd[j] = __ldg(batch + dv[j]); }
#pragma unroll
        for (int j = 0; j < 8; j++) {
            v[j] = (bs[j] == bd[j]);
            if (v[j]) { atomicAdd(&g_deg[sv[j]], 1); cnt++; }
        }
    } else {
#pragma unroll
        for (int j = 0; j < 8; j++) v[j] = false;
    }
    int lane = threadIdx.x & 31;
    int incl = cnt;
#pragma unroll
    for (int off = 1; off < 32; off <<= 1) {
        int nv = __shfl_up_sync(0xffffffffu, incl, off);
        if (lane >= off) incl += nv;
    }
    int total = __shfl_sync(0xffffffffu, incl, 31);
    int basew = 0;
    if (lane == 31 && total > 0) basew = atomicAdd(&g_vcnt, total);
    basew = __shfl_sync(0xffffffffu, basew, 31);
    int pos = basew + incl - cnt;
#pragma unroll
    for (int j = 0; j < 8; j++) {
        if (v[j]) g_ve[pos++] = make_int2(sv[j], dv[j]);
    }
}

// ---------------- K2: encode nodes (token histogram) + dinv + Ms1; zero agg1 ----------------
__global__ void k_encode(const int* __restrict__ seq, const float* __restrict__ xcov,
                         const float* __restrict__ embed, const float* __restrict__ w1,
                         const float* __restrict__ b1) {
    __shared__ float s_emb[6 * 16];
    __shared__ float s_w1[17 * 16];
    __shared__ float s_b1[16];
    int t = threadIdx.x;
    for (int j = t; j < 96; j += blockDim.x) s_emb[j] = embed[j];
    for (int j = t; j < 272; j += blockDim.x) s_w1[j] = w1[j];
    if (t < 16) s_b1[t] = b1[t];
    __syncthreads();

    int n = blockIdx.x * blockDim.x + t;
    if (n >= NND) return;

    float dinv = rsqrtf((float)g_deg[n] + 1.0f + 1e-8f);
    g_dinv[n] = dinv;

    float zr[8] = {0.f,0.f,0.f,0.f,0.f,0.f,0.f,0.f};
    stg256f(&g_agg1[2 * n + 0], zr);
    stg256f(&g_agg1[2 * n + 1], zr);

    int c1 = 0, c2 = 0, c3 = 0, c4 = 0, c5 = 0;
    const V8* tp = reinterpret_cast<const V8*>(seq + (long)n * LTOK);
#pragma unroll
    for (int i = 0; i < 8; i++) {
        V8 v = ldg256u(tp + i);
        int tok[8] = {(int)v.a.x, (int)v.a.y, (int)v.a.z, (int)v.a.w,
                      (int)v.b.x, (int)v.b.y, (int)v.b.z, (int)v.b.w};
#pragma unroll
        for (int j = 0; j < 8; j++) {
            int tk = tok[j];
            c1 += (tk == 1); c2 += (tk == 2); c3 += (tk == 3);
            c4 += (tk == 4); c5 += (tk == 5);
        }
    }
    int nz = c1 + c2 + c3 + c4 + c5;
    float inv = 1.0f / fmaxf((float)nz, 1.0f);
    float f1 = c1 * inv, f2 = c2 * inv, f3 = c3 * inv, f4 = c4 * inv, f5 = c5 * inv;

    float x[17];
#pragma unroll
    for (int k = 0; k < 16; k++) {
        x[k] = f1 * s_emb[16 + k] + f2 * s_emb[32 + k] + f3 * s_emb[48 + k]
             + f4 * s_emb[64 + k] + f5 * s_emb[80 + k];
    }
    x[16] = xcov[n];

    float m[16];
#pragma unroll
    for (int k = 0; k < 16; k++) {
        float s = s_b1[k];
#pragma unroll
        for (int j = 0; j < 17; j++) s += x[j] * s_w1[j * 16 + k];
        m[k] = s * dinv;  // pre-scale by dinv
    }
    stg256f(&g_Ms1[2 * n + 0], m);
    stg256f(&g_Ms1[2 * n + 1], m + 8);
}

// ---------------- K3/K5: aggregation, 2 edges/thread, v8 row loads ----------------
template <int LAYER>
__global__ void k_aggregate() {
    int cnt = g_vcnt;
    int npair = (cnt + 1) >> 1;
    int stride = gridDim.x * blockDim.x;
    const F8* Ms = (LAYER == 0) ? g_Ms1 : g_Ms2;
    float* agg = (LAYER == 0) ? (float*)g_agg1 : (float*)g_agg2;
    for (int i = blockIdx.x * blockDim.x + threadIdx.x; i < npair; i += stride) {
        int4 e2 = *reinterpret_cast<const int4*>(&g_ve[2 * i]);
        bool second = (2 * i + 1 < cnt);
        F8 r0a = ldg256f(Ms + 2 * e2.y + 0);
        F8 r0b = ldg256f(Ms + 2 * e2.y + 1);
        F8 r1a, r1b;
        if (second) {
            r1a = ldg256f(Ms + 2 * e2.w + 0);
            r1b = ldg256f(Ms + 2 * e2.w + 1);
        }
        float* ap0 = agg + e2.x * 16;
        red_add_v4(ap0 + 0,  r0a.a);
        red_add_v4(ap0 + 4,  r0a.b);
        red_add_v4(ap0 + 8,  r0b.a);
        red_add_v4(ap0 + 12, r0b.b);
        if (second) {
            float* ap1 = agg + e2.z * 16;
            red_add_v4(ap1 + 0,  r1a.a);
            red_add_v4(ap1 + 4,  r1a.b);
            red_add_v4(ap1 + 8,  r1b.a);
            red_add_v4(ap1 + 12, r1b.b);
        }
    }
}

// ---------------- K4: H1 = relu(dinv*(agg1+Ms1)); Ms2 = dinv*(H1@w2+b2); zero agg2 ----------------
__global__ void k_finalize1(const float* __restrict__ w2, const float* __restrict__ b2) {
    __shared__ float sW[16 * 16];
    __shared__ float sb[16];
    int t = threadIdx.x;
    for (int j = t; j < 256; j += blockDim.x) sW[j] = w2[j];
    if (t < 16) sb[t] = b2[t];
    __syncthreads();

    int n = blockIdx.x * blockDim.x + t;
    if (n >= NND) return;
    float dinv = g_dinv[n];

    float zr[8] = {0.f,0.f,0.f,0.f,0.f,0.f,0.f,0.f};
    stg256f(&g_agg2[2 * n + 0], zr);
    stg256f(&g_agg2[2 * n + 1], zr);

    F8 aa = ldg256f(&g_agg1[2 * n + 0]);
    F8 ab = ldg256f(&g_agg1[2 * n + 1]);
    F8 ma = ldg256f(&g_Ms1[2 * n + 0]);
    F8 mb = ldg256f(&g_Ms1[2 * n + 1]);
    const float* av = reinterpret_cast<const float*>(&aa);
    const float* mv = reinterpret_cast<const float*>(&ma);
    float h[16];
#pragma unroll
    for (int k = 0; k < 8; k++) h[k] = fmaxf(dinv * (av[k] + mv[k]), 0.f);
    const float* av2 = reinterpret_cast<const float*>(&ab);
    const float* mv2 = reinterpret_cast<const float*>(&mb);
#pragma unroll
    for (int k = 0; k < 8; k++) h[8 + k] = fmaxf(dinv * (av2[k] + mv2[k]), 0.f);

    float m2[16];
#pragma unroll
    for (int k = 0; k < 16; k++) {
        float s = sb[k];
#pragma unroll
        for (int j = 0; j < 16; j++) s += h[j] * sW[j * 16 + k];
        m2[k] = s * dinv;  // pre-scale
    }
    stg256f(&g_Ms2[2 * n + 0], m2);
    stg256f(&g_Ms2[2 * n + 1], m2 + 8);
}

// ---------------- K6: H2 -> A,B stored fp16 (v8 store) ----------------
__global__ void k_finalize2(const float* __restrict__ we1, const float* __restrict__ be1) {
    __shared__ float sW[32 * 16];
    __shared__ float sb[16];
    int t = threadIdx.x;
    for (int j = t; j < 512; j += blockDim.x) sW[j] = we1[j];
    if (t < 16) sb[t] = be1[t];
    __syncthreads();

    int n = blockIdx.x * blockDim.x + t;
    if (n >= NND) return;
    float dinv = g_dinv[n];
    F8 aa = ldg256f(&g_agg2[2 * n + 0]);
    F8 ab = ldg256f(&g_agg2[2 * n + 1]);
    F8 ma = ldg256f(&g_Ms2[2 * n + 0]);
    F8 mb = ldg256f(&g_Ms2[2 * n + 1]);
    const float* av0 = reinterpret_cast<const float*>(&aa);
    const float* mv0 = reinterpret_cast<const float*>(&ma);
    const float* av1 = reinterpret_cast<const float*>(&ab);
    const float* mv1 = reinterpret_cast<const float*>(&mb);
    float h[16];
#pragma unroll
    for (int k = 0; k < 8; k++) h[k] = fmaxf(dinv * (av0[k] + mv0[k]), 0.f);
#pragma unroll
    for (int k = 0; k < 8; k++) h[8 + k] = fmaxf(dinv * (av1[k] + mv1[k]), 0.f);

    float av[16], bv[16];
#pragma unroll
    for (int k = 0; k < 16; k++) {
        float sa = sb[k];
        float sbv = 0.f;
#pragma unroll
        for (int j = 0; j < 16; j++) {
            sa  += h[j] * sW[j * 16 + k];
            sbv += h[j] * sW[(16 + j) * 16 + k];
        }
        av[k] = sa; bv[k] = sbv;
    }
    unsigned wa[8], wb[8];
#pragma unroll
    for (int i = 0; i < 8; i++) {
        __half2 pa = __floats2half2_rn(av[2 * i], av[2 * i + 1]);
        __half2 pb = __floats2half2_rn(bv[2 * i], bv[2 * i + 1]);
        wa[i] = *reinterpret_cast<unsigned*>(&pa);
        wb[i] = *reinterpret_cast<unsigned*>(&pb);
    }
    stg256u(&g_Ah[n], wa);
    stg256u(&g_Bh[n], wb);
}

// ---------------- K7: edge MLP output (4 edges/thread, v8 gathers) ----------------
__global__ void k_edge_out(const int* __restrict__ ei, const float* __restrict__ eattr,
                           const float* __restrict__ we1, const float* __restrict__ we2,
                           const float* __restrict__ be2, float* __restrict__ out) {
    __shared__ float sWc[5 * 16];  // we1 rows 32..36
    __shared__ float sW2[16];
    __shared__ float sb2;
    int t = threadIdx.x;
    for (int j = t; j < 80; j += blockDim.x) sWc[j] = we1[32 * 16 + j];
    if (t < 16) sW2[t] = we2[t];
    if (t == 0) sb2 = be2[0];
    __syncthreads();

    int gt = blockIdx.x * blockDim.x + t;
    int base_e = gt * 4;                    // NE % (4*256) == 0
    int4 s4 = *reinterpret_cast<const int4*>(ei + base_e);
    int4 d4 = *reinterpret_cast<const int4*>(ei + NE + base_e);
    int sv[4] = {s4.x, s4.y, s4.z, s4.w};
    int dv[4] = {d4.x, d4.y, d4.z, d4.w};

    // first pair's gathers (one v8 per row)
    V8 pa[2], pb[2];
#pragma unroll
    for (int j = 0; j < 2; j++) {
        pa[j] = ldg256u(&g_Ah[sv[j]]);
        pb[j] = ldg256u(&g_Bh[dv[j]]);
    }
    // eattr stream load overlaps the gathers
    float ea[20];
    const float4* ep = reinterpret_cast<const float4*>(eattr + (long)base_e * EF);
#pragma unroll
    for (int i = 0; i < 5; i++) {
        float4 v = ep[i];
        ea[4 * i + 0] = v.x; ea[4 * i + 1] = v.y; ea[4 * i + 2] = v.z; ea[4 * i + 3] = v.w;
    }

    float res[4];
#pragma unroll
    for (int p = 0; p < 2; p++) {
        if (p == 1) {
#pragma unroll
            for (int j = 0; j < 2; j++) {
                pa[j] = ldg256u(&g_Ah[sv[2 + j]]);
                pb[j] = ldg256u(&g_Bh[dv[2 + j]]);
            }
        }
#pragma unroll
        for (int q = 0; q < 2; q++) {
            int j = 2 * p + q;
            unsigned aw[8] = {pa[q].a.x, pa[q].a.y, pa[q].a.z, pa[q].a.w,
                              pa[q].b.x, pa[q].b.y, pa[q].b.z, pa[q].b.w};
            unsigned bw[8] = {pb[q].a.x, pb[q].a.y, pb[q].a.z, pb[q].a.w,
                              pb[q].b.x, pb[q].b.y, pb[q].b.z, pb[q].b.w};
            float h[16];
#pragma unroll
            for (int i = 0; i < 8; i++) {
                float2 fa = __half22float2(*reinterpret_cast<__half2*>(&aw[i]));
                float2 fb = __half22float2(*reinterpret_cast<__half2*>(&bw[i]));
                h[2 * i + 0] = fa.x + fb.x;
                h[2 * i + 1] = fa.y + fb.y;
            }
#pragma unroll
            for (int r = 0; r < EF; r++) {
                float eav = ea[5 * j + r];
#pragma unroll
                for (int k = 0; k < 16; k++) h[k] += eav * sWc[r * 16 + k];
            }
            float acc = sb2;
#pragma unroll
            for (int k = 0; k < 16; k++) acc += fmaxf(h[k], 0.f) * sW2[k];
            res[j] = acc;
        }
    }
    *reinterpret_cast<float4*>(out + base_e) = make_float4(res[0], res[1], res[2], res[3]);
}

extern "C" void kernel_launch(void* const* d_in, const int* in_sizes, int n_in,
                              void* d_out, int out_size) {
    const int*   seq   = (const int*)d_in[0];
    const float* xcov  = (const float*)d_in[1];
    const int*   ei    = (const int*)d_in[2];
    const float* eattr = (const float*)d_in[3];
    const int*   batch = (const int*)d_in[4];
    const float* embed = (const float*)d_in[5];
    const float* w1    = (const float*)d_in[6];
    const float* b1    = (const float*)d_in[7];
    const float* w2    = (const float*)d_in[8];
    const float* b2    = (const float*)d_in[9];
    const float* we1   = (const float*)d_in[10];
    const float* be1   = (const float*)d_in[11];
    const float* we2   = (const float*)d_in[12];
    const float* be2   = (const float*)d_in[13];
    float* out = (float*)d_out;

    const int TB = 256;
    const int nb_e4 = NE / (TB * 4);              // 3125
    const int nb_e8 = (NE / 8 + TB - 1) / TB;     // 1563
    const int nb_n = (NND + TB - 1) / TB;

    k_zero_small<<<nb_n, TB>>>();
    k_deg_compact<<<nb_e8, TB>>>(ei, batch);
    k_encode<<<nb_n, TB>>>(seq, xcov, embed, w1, b1);
    k_aggregate<0><<<256, TB>>>();
    k_finalize1<<<nb_n, TB>>>(w2, b2);
    k_aggregate<1><<<256, TB>>>();
    k_finalize2<<<nb_n, TB>>>(we1, be1);
    k_edge_out<<<nb_e4, TB>>>(ei, eattr, we1, we2, be2, out);
}